// round 15
// baseline (speedup 1.0000x reference)
#include <cuda_runtime.h>
#include <cstdint>
#include <math.h>

#define NBATCH 32
#define C_ST_  2048
#define C_LT_  2048
#define LAT_   512
#define S_     512
#define L_     2048

// ---------------- scratch (__device__ globals; no allocation) ----------------
__device__ float g_thetaOS[(size_t)NBATCH * LAT_ * S_];   // (n, LAT, S) theta[o][s], rounded
__device__ float g_pg   [(size_t)NBATCH * 1024 * L_];     // (n, 1024, L): rows 0..511 phi, 512..1023 g
__device__ float g_sc   [(size_t)NBATCH * S_ * L_];       // (n, S, L)
__device__ float g_attn [(size_t)NBATCH * LAT_ * S_];     // (n, LAT, S) attn[c][s]
__device__ float g_nrm  [(size_t)NBATCH * LAT_ * S_];     // (n, LAT, S) rounded
__device__ float2 g_part[NBATCH * 16];
__device__ float g_stats[NBATCH * 2];
__device__ float g_wstR [(size_t)LAT_ * C_ST_];           // tf32-rounded weights
__device__ float g_wLG  [(size_t)1024 * C_LT_];           // stacked [w_lt; w_g], tf32-rounded
__device__ float g_bLG  [1024];                           // stacked [b_lt; b_g]
__device__ float g_woutR[(size_t)C_ST_ * LAT_];

// ---------------- helpers ----------------
__device__ __forceinline__ uint32_t smem_u32(const void* p) {
    uint32_t a;
    asm("{ .reg .u64 t; cvta.to.shared.u64 t, %1; cvt.u32.u64 %0, t; }" : "=r"(a) : "l"(p));
    return a;
}
__device__ __forceinline__ float to_tf32(float x) {
    float y;
    asm("cvt.rna.tf32.f32 %0, %1;" : "=f"(y) : "f"(x));
    return y;
}
__device__ __forceinline__ void cvt_frag(uint32_t& u) {
    float f = __uint_as_float(u);
    u = __float_as_uint(to_tf32(f));
}
#define CP_ASYNC16(dst, src) \
    asm volatile("cp.async.cg.shared.global [%0], [%1], 16;" :: "r"(dst), "l"(src))
#define CP_COMMIT() asm volatile("cp.async.commit_group;")
#define CP_WAIT1()  asm volatile("cp.async.wait_group 1;")
#define CP_WAIT2()  asm volatile("cp.async.wait_group 2;")

__device__ __forceinline__ uint32_t lds32(uint32_t addr) {
    uint32_t v;
    asm volatile("ld.shared.b32 %0, [%1];" : "=r"(v) : "r"(addr));
    return v;
}
__device__ __forceinline__ void mma_tf32(float* d, const uint32_t* a, const uint32_t* b) {
    asm volatile(
        "mma.sync.aligned.m16n8k8.row.col.f32.tf32.tf32.f32 "
        "{%0,%1,%2,%3},{%4,%5,%6,%7},{%8,%9},{%0,%1,%2,%3};"
        : "+f"(d[0]), "+f"(d[1]), "+f"(d[2]), "+f"(d[3])
        : "r"(a[0]), "r"(a[1]), "r"(a[2]), "r"(a[3]), "r"(b[0]), "r"(b[1]));
}

// ================= generic 128x128x32 GEMM (HW-validated; used for attn NT) ==========
#define NST 3
#define STAGE_BYTES 32768
#define GEMM_SMEM (NST * STAGE_BYTES)     // 96 KB

template <int ATR, int BTR, int RA, int RB>
__global__ __launch_bounds__(256, 2)
void gemm_mma(const float* __restrict__ Ag, const float* __restrict__ Bg,
              float* __restrict__ Cg, const float* __restrict__ bias,
              int K, int lda, int ldb, int ldc,
              size_t sA, size_t sB, size_t sC, float alpha,
              int bias_mode, int round_out)
{
    extern __shared__ char smem[];
    const uint32_t sbase = smem_u32(smem);
    const int tid  = threadIdx.x;
    const int wid  = tid >> 5;
    const int lane = tid & 31;
    const int q    = lane >> 2;
    const int mq   = lane & 3;
    const int wm   = wid >> 2;
    const int wn   = wid & 3;
    const int m0   = blockIdx.y * 128;
    const int n0   = blockIdx.x * 128;

    const float* A = Ag + (size_t)blockIdx.z * sA + (ATR ? (size_t)m0 : (size_t)m0 * lda);
    const float* B = Bg + (size_t)blockIdx.z * sB + (BTR ? (size_t)n0 : (size_t)n0 * ldb);
    float*       C = Cg + (size_t)blockIdx.z * sC;

    size_t   gAoff[4], gBoff[4];
    uint32_t sAoff[4], sBoff[4];
#pragma unroll
    for (int j = 0; j < 4; j++) {
        int id = tid + 256 * j;
        if (ATR) {
            int kr = id >> 5, c4 = id & 31;
            gAoff[j] = (size_t)kr * lda + c4 * 4;
            sAoff[j] = kr * 512 + ((c4 * 16) ^ ((kr & 3) << 5));
        } else {
            int r = id >> 3, c4 = id & 7;
            gAoff[j] = (size_t)r * lda + c4 * 4;
            sAoff[j] = r * 128 + ((c4 ^ (r & 7)) << 4);
        }
        if (BTR) {
            int kr = id >> 5, c4 = id & 31;
            gBoff[j] = (size_t)kr * ldb + c4 * 4;
            sBoff[j] = 16384 + kr * 512 + ((c4 * 16) ^ ((kr & 3) << 5));
        } else {
            int r = id >> 3, c4 = id & 7;
            gBoff[j] = (size_t)r * ldb + c4 * 4;
            sBoff[j] = 16384 + r * 128 + ((c4 ^ (r & 7)) << 4);
        }
    }
    const size_t aAdv = ATR ? (size_t)32 * lda : (size_t)32;
    const size_t bAdv = BTR ? (size_t)32 * ldb : (size_t)32;
    const int KT = K >> 5;

#define ISSUE(it_) do {                                                  \
        int s_ = (it_) % NST;                                            \
        uint32_t base_ = sbase + s_ * STAGE_BYTES;                       \
        const float* Ai_ = A + (size_t)(it_) * aAdv;                     \
        const float* Bi_ = B + (size_t)(it_) * bAdv;                     \
        _Pragma("unroll")                                                \
        for (int j = 0; j < 4; j++) {                                    \
            CP_ASYNC16(base_ + sAoff[j], Ai_ + gAoff[j]);                \
            CP_ASYNC16(base_ + sBoff[j], Bi_ + gBoff[j]);                \
        }                                                                \
    } while (0)

    ISSUE(0); CP_COMMIT();
    ISSUE(1); CP_COMMIT();

    float acc[4][4][4];
#pragma unroll
    for (int mi = 0; mi < 4; mi++)
#pragma unroll
        for (int ni = 0; ni < 4; ni++)
#pragma unroll
            for (int r = 0; r < 4; r++) acc[mi][ni][r] = 0.f;

    uint32_t aBase[4], bBase[4];
    uint32_t amLo[4], amHi[4];
    uint32_t bnLo[4];
    const uint32_t swz = (uint32_t)(mq << 5);
#pragma unroll
    for (int mi = 0; mi < 4; mi++) {
        int m = wm * 64 + mi * 16 + q;
        aBase[mi] = m * 128 + mq * 4;
        amLo[mi]  = ((uint32_t)(m * 4)) ^ swz;
        amHi[mi]  = ((uint32_t)((m + 8) * 4)) ^ swz;
    }
#pragma unroll
    for (int ni = 0; ni < 4; ni++) {
        int n = wn * 32 + ni * 8 + q;
        bBase[ni] = n * 128 + mq * 4 + 16384;
        bnLo[ni]  = ((uint32_t)(n * 4)) ^ swz;
    }

    for (int it = 0; it < KT; ++it) {
        CP_WAIT1();
        __syncthreads();
        if (it + 2 < KT) ISSUE(it + 2);
        CP_COMMIT();

        const uint32_t buf = sbase + (it % NST) * STAGE_BYTES;
#pragma unroll
        for (int ki = 0; ki < 4; ki++) {
            uint32_t a[4][4], b[4][2];
            if (ATR) {
                const uint32_t kA = buf + ki * 4096 + mq * 512;
#pragma unroll
                for (int mi = 0; mi < 4; mi++) {
                    a[mi][0] = lds32(kA + amLo[mi]);
                    a[mi][1] = lds32(kA + amHi[mi]);
                    a[mi][2] = lds32(kA + 2048 + amLo[mi]);
                    a[mi][3] = lds32(kA + 2048 + amHi[mi]);
                }
            } else {
                const uint32_t c0 = (uint32_t)(((2 * ki) ^ q) << 4);
                const uint32_t c1 = (uint32_t)(((2 * ki + 1) ^ q) << 4);
#pragma unroll
                for (int mi = 0; mi < 4; mi++) {
                    uint32_t ad = buf + aBase[mi];
                    a[mi][0] = lds32(ad + c0);
                    a[mi][1] = lds32(ad + 1024 + c0);
                    a[mi][2] = lds32(ad + c1);
                    a[mi][3] = lds32(ad + 1024 + c1);
                }
            }
            if (BTR) {
                const uint32_t kB = buf + 16384 + ki * 4096 + mq * 512;
#pragma unroll
                for (int ni = 0; ni < 4; ni++) {
                    b[ni][0] = lds32(kB + bnLo[ni]);
                    b[ni][1] = lds32(kB + 2048 + bnLo[ni]);
                }
            } else {
                const uint32_t c0 = (uint32_t)(((2 * ki) ^ q) << 4);
                const uint32_t c1 = (uint32_t)(((2 * ki + 1) ^ q) << 4);
#pragma unroll
                for (int ni = 0; ni < 4; ni++) {
                    uint32_t bd = buf + bBase[ni];
                    b[ni][0] = lds32(bd + c0);
                    b[ni][1] = lds32(bd + c1);
                }
            }
            if (RA) {
#pragma unroll
                for (int mi = 0; mi < 4; mi++)
#pragma unroll
                    for (int r = 0; r < 4; r++) cvt_frag(a[mi][r]);
            }
            if (RB) {
#pragma unroll
                for (int ni = 0; ni < 4; ni++) { cvt_frag(b[ni][0]); cvt_frag(b[ni][1]); }
            }
#pragma unroll
            for (int mi = 0; mi < 4; mi++)
#pragma unroll
                for (int ni = 0; ni < 4; ni++)
                    mma_tf32(acc[mi][ni], a[mi], b[ni]);
        }
    }
#undef ISSUE

#pragma unroll
    for (int mi = 0; mi < 4; mi++) {
        const int row = m0 + wm * 64 + mi * 16 + q;
        float bm0 = 0.f, bm8 = 0.f;
        if (bias_mode == 2) { bm0 = __ldg(bias + row); bm8 = __ldg(bias + row + 8); }
#pragma unroll
        for (int ni = 0; ni < 4; ni++) {
            const int col = n0 + wn * 32 + ni * 8 + 2 * mq;
            float bn0 = 0.f, bn1 = 0.f;
            if (bias_mode == 1) { bn0 = __ldg(bias + col); bn1 = __ldg(bias + col + 1); }
            float v00 = acc[mi][ni][0] * alpha;
            float v01 = acc[mi][ni][1] * alpha;
            float v10 = acc[mi][ni][2] * alpha;
            float v11 = acc[mi][ni][3] * alpha;
            if (bias_mode == 1) { v00 += bn0; v01 += bn1; v10 += bn0; v11 += bn1; }
            else if (bias_mode == 2) { v00 += bm0; v01 += bm0; v10 += bm8; v11 += bm8; }
            if (round_out) {
                v00 = to_tf32(v00); v01 = to_tf32(v01);
                v10 = to_tf32(v10); v11 = to_tf32(v11);
            }
            *(float2*)(C + (size_t)row * ldc + col)       = make_float2(v00, v01);
            *(float2*)(C + (size_t)(row + 8) * ldc + col) = make_float2(v10, v11);
        }
    }
}

// ================= big-tile GEMM: 128m x 256n x 32k, D = alpha*A@B (+row bias) ======
// ATR=0: A [M][K] k-contig.  ATR=1: A [K][M] m-contig (lda = k-row stride).
// B: [K][N] n-contig. RBC: cvt.rna B fragments. 4 stages, prefetch depth 3, 1 CTA/SM.
#define BNST 4
#define BSTG (16384 + 32768)            // A 16KB + B 32KB = 48KB/stage
#define GEMM_BIG_SMEM (BNST * BSTG)     // 192 KB

template <int ATR, int RBC>
__global__ __launch_bounds__(256, 1)
void gemm_big(const float* __restrict__ Ag, const float* __restrict__ Bg,
              float* __restrict__ Cg, const float* __restrict__ bias,
              int K, int lda, int ldb, int ldc,
              size_t sA, size_t sB, size_t sC, float alpha, int round_out)
{
    extern __shared__ char smem[];
    const uint32_t sbase = smem_u32(smem);
    const int tid  = threadIdx.x;
    const int wid  = tid >> 5;
    const int lane = tid & 31;
    const int q    = lane >> 2;
    const int mq   = lane & 3;
    const int wm   = wid >> 2;        // 0..1
    const int wn   = wid & 3;         // 0..3
    const int m0   = blockIdx.y * 128;
    const int n0   = blockIdx.x * 256;

    const float* A = Ag + (size_t)blockIdx.z * sA + (ATR ? (size_t)m0 : (size_t)m0 * lda);
    const float* B = Bg + (size_t)blockIdx.z * sB + n0;
    float*       C = Cg + (size_t)blockIdx.z * sC;

    size_t   gAoff[4];
    uint32_t sAoff[4];
#pragma unroll
    for (int j = 0; j < 4; j++) {
        int id = tid + 256 * j;
        if (ATR) {
            int kr = id >> 5, c4 = id & 31;       // 32 k-rows x 32 chunks (128 m-floats)
            gAoff[j] = (size_t)kr * lda + c4 * 4;
            sAoff[j] = kr * 512 + ((c4 * 16) ^ ((kr & 3) << 5));
        } else {
            int r = id >> 3, c4 = id & 7;
            gAoff[j] = (size_t)r * lda + c4 * 4;
            sAoff[j] = r * 128 + ((c4 ^ (r & 7)) << 4);
        }
    }
    size_t   gBoff[8];
    uint32_t sBoff[8];
#pragma unroll
    for (int j = 0; j < 8; j++) {
        int id = tid + 256 * j;
        int kr = id >> 6, c4 = id & 63;
        gBoff[j] = (size_t)kr * ldb + c4 * 4;
        sBoff[j] = 16384 + kr * 1024 + (((uint32_t)c4 << 4) ^ ((uint32_t)(kr & 3) << 5));
    }
    const size_t aAdv = ATR ? (size_t)32 * lda : (size_t)32;
    const int KT = K >> 5;

#define BISSUE(it_) do {                                                 \
        int s_ = (it_) % BNST;                                           \
        uint32_t base_ = sbase + s_ * BSTG;                              \
        const float* Ai_ = A + (size_t)(it_) * aAdv;                     \
        const float* Bi_ = B + (size_t)(it_) * 32 * ldb;                 \
        _Pragma("unroll")                                                \
        for (int j = 0; j < 4; j++) CP_ASYNC16(base_ + sAoff[j], Ai_ + gAoff[j]); \
        _Pragma("unroll")                                                \
        for (int j = 0; j < 8; j++) CP_ASYNC16(base_ + sBoff[j], Bi_ + gBoff[j]); \
    } while (0)

    BISSUE(0); CP_COMMIT();
    BISSUE(1); CP_COMMIT();
    BISSUE(2); CP_COMMIT();

    float acc[4][8][4];
#pragma unroll
    for (int mi = 0; mi < 4; mi++)
#pragma unroll
        for (int ni = 0; ni < 8; ni++)
#pragma unroll
            for (int r = 0; r < 4; r++) acc[mi][ni][r] = 0.f;

    uint32_t aBase[4], amLo[4], amHi[4], bnOff[8];
    const uint32_t swz = (uint32_t)(mq << 5);
#pragma unroll
    for (int mi = 0; mi < 4; mi++) {
        int m = wm * 64 + mi * 16 + q;
        aBase[mi] = m * 128 + mq * 4;
        amLo[mi]  = ((uint32_t)(m * 4)) ^ swz;
        amHi[mi]  = ((uint32_t)((m + 8) * 4)) ^ swz;
    }
#pragma unroll
    for (int ni = 0; ni < 8; ni++)
        bnOff[ni] = ((uint32_t)((wn * 64 + ni * 8 + q) * 4)) ^ swz;

    for (int it = 0; it < KT; ++it) {
        CP_WAIT2();
        __syncthreads();
        if (it + 3 < KT) BISSUE(it + 3);
        CP_COMMIT();

        const uint32_t buf = sbase + (it % BNST) * BSTG;
#pragma unroll
        for (int ki = 0; ki < 4; ki++) {
            uint32_t a[4][4], b[8][2];
            if (ATR) {
                const uint32_t kA = buf + ki * 4096 + mq * 512;
#pragma unroll
                for (int mi = 0; mi < 4; mi++) {
                    a[mi][0] = lds32(kA + amLo[mi]);
                    a[mi][1] = lds32(kA + amHi[mi]);
                    a[mi][2] = lds32(kA + 2048 + amLo[mi]);
                    a[mi][3] = lds32(kA + 2048 + amHi[mi]);
                }
            } else {
                const uint32_t c0 = (uint32_t)(((2 * ki) ^ q) << 4);
                const uint32_t c1 = (uint32_t)(((2 * ki + 1) ^ q) << 4);
#pragma unroll
                for (int mi = 0; mi < 4; mi++) {
                    uint32_t ad = buf + aBase[mi];
                    a[mi][0] = lds32(ad + c0);
                    a[mi][1] = lds32(ad + 1024 + c0);
                    a[mi][2] = lds32(ad + c1);
                    a[mi][3] = lds32(ad + 1024 + c1);
                }
            }
            const uint32_t kB0 = buf + 16384 + (8 * ki + mq) * 1024;
#pragma unroll
            for (int ni = 0; ni < 8; ni++) {
                b[ni][0] = lds32(kB0 + bnOff[ni]);
                b[ni][1] = lds32(kB0 + 4096 + bnOff[ni]);
            }
            if (RBC) {
#pragma unroll
                for (int ni = 0; ni < 8; ni++) { cvt_frag(b[ni][0]); cvt_frag(b[ni][1]); }
            }
#pragma unroll
            for (int mi = 0; mi < 4; mi++)
#pragma unroll
                for (int ni = 0; ni < 8; ni++)
                    mma_tf32(acc[mi][ni], a[mi], b[ni]);
        }
    }
#undef BISSUE

#pragma unroll
    for (int mi = 0; mi < 4; mi++) {
        const int row = m0 + wm * 64 + mi * 16 + q;
        float bm0 = 0.f, bm8 = 0.f;
        if (bias) { bm0 = __ldg(bias + row); bm8 = __ldg(bias + row + 8); }
#pragma unroll
        for (int ni = 0; ni < 8; ni++) {
            const int col = n0 + wn * 64 + ni * 8 + 2 * mq;
            float v00 = acc[mi][ni][0] * alpha + bm0;
            float v01 = acc[mi][ni][1] * alpha + bm0;
            float v10 = acc[mi][ni][2] * alpha + bm8;
            float v11 = acc[mi][ni][3] * alpha + bm8;
            if (round_out) {
                v00 = to_tf32(v00); v01 = to_tf32(v01);
                v10 = to_tf32(v10); v11 = to_tf32(v11);
            }
            *(float2*)(C + (size_t)row * ldc + col)       = make_float2(v00, v01);
            *(float2*)(C + (size_t)(row + 8) * ldc + col) = make_float2(v10, v11);
        }
    }
}

// ---------------- prepass kernels ----------------
__global__ __launch_bounds__(256)
void round_copy4_kernel(const float* __restrict__ i0, const float* __restrict__ i1,
                        const float* __restrict__ i2, const float* __restrict__ i3,
                        float* __restrict__ o0, float* __restrict__ o1,
                        float* __restrict__ o2, float* __restrict__ o3)
{
    size_t idx = (size_t)blockIdx.x * blockDim.x + threadIdx.x;
    int seg    = (int)(idx >> 18);
    size_t loc = idx & 262143;
    const float* in; float* out;
    if      (seg == 0) { in = i0; out = o0; }
    else if (seg == 1) { in = i1; out = o1; }
    else if (seg == 2) { in = i2; out = o2; }
    else               { in = i3; out = o3; }
    float4 v = ((const float4*)in)[loc];
    v.x = to_tf32(v.x); v.y = to_tf32(v.y); v.z = to_tf32(v.z); v.w = to_tf32(v.w);
    ((float4*)out)[loc] = v;
}

__global__ void stack_bias_kernel(const float* __restrict__ b0, const float* __restrict__ b1,
                                  float* __restrict__ out)
{
    int i = threadIdx.x + blockIdx.x * blockDim.x;
    out[i] = (i < 512) ? b0[i] : b1[i - 512];
}

// ---------------- softmax over L=2048 ----------------
__global__ __launch_bounds__(256)
void softmax_kernel(float* __restrict__ sc)
{
    float* p = sc + (size_t)blockIdx.x * L_;
    const int tid = threadIdx.x;
    float v[8];
    float mx = -1e30f;
#pragma unroll
    for (int i = 0; i < 8; i++) { v[i] = p[tid + i * 256]; mx = fmaxf(mx, v[i]); }
#pragma unroll
    for (int o = 16; o; o >>= 1) mx = fmaxf(mx, __shfl_xor_sync(0xffffffffu, mx, o));
    __shared__ float smax[8], ssum[8];
    if ((tid & 31) == 0) smax[tid >> 5] = mx;
    __syncthreads();
    float m2 = smax[0];
#pragma unroll
    for (int i = 1; i < 8; i++) m2 = fmaxf(m2, smax[i]);
    float s = 0.f;
#pragma unroll
    for (int i = 0; i < 8; i++) { v[i] = __expf(v[i] - m2); s += v[i]; }
#pragma unroll
    for (int o = 16; o; o >>= 1) s += __shfl_xor_sync(0xffffffffu, s, o);
    if ((tid & 31) == 0) ssum[tid >> 5] = s;
    __syncthreads();
    float tot = 0.f;
#pragma unroll
    for (int i = 0; i < 8; i++) tot += ssum[i];
    float inv = 1.f / tot;
#pragma unroll
    for (int i = 0; i < 8; i++) p[tid + i * 256] = to_tf32(v[i] * inv);
}

// ---------------- layernorm stats (two-phase) ----------------
__global__ __launch_bounds__(256)
void ln_part_kernel(const float* __restrict__ x, float2* __restrict__ part)
{
    const int batch = blockIdx.y;
    const int p     = blockIdx.x;
    const float4* xb = (const float4*)(x + (size_t)batch * (LAT_ * S_) + p * 16384);
    float s = 0.f, ss = 0.f;
#pragma unroll
    for (int i = 0; i < 16; i++) {
        float4 v = xb[threadIdx.x + i * 256];
        s  += v.x + v.y + v.z + v.w;
        ss += v.x * v.x + v.y * v.y + v.z * v.z + v.w * v.w;
    }
#pragma unroll
    for (int o = 16; o; o >>= 1) {
        s  += __shfl_xor_sync(0xffffffffu, s, o);
        ss += __shfl_xor_sync(0xffffffffu, ss, o);
    }
    __shared__ float rs[8], rss[8];
    if ((threadIdx.x & 31) == 0) { rs[threadIdx.x >> 5] = s; rss[threadIdx.x >> 5] = ss; }
    __syncthreads();
    if (threadIdx.x == 0) {
        float S = 0.f, SSq = 0.f;
#pragma unroll
        for (int i = 0; i < 8; i++) { S += rs[i]; SSq += rss[i]; }
        part[batch * 16 + p] = make_float2(S, SSq);
    }
}

__global__ void ln_final_kernel(const float2* __restrict__ part, float* __restrict__ stats)
{
    int b = threadIdx.x;
    float S = 0.f, SSq = 0.f;
#pragma unroll
    for (int i = 0; i < 16; i++) {
        float2 v = part[b * 16 + i];
        S += v.x; SSq += v.y;
    }
    const float invN = 1.f / (float)(LAT_ * S_);
    float mu  = S * invN;
    float var = SSq * invN - mu * mu;
    stats[b * 2 + 0] = mu;
    stats[b * 2 + 1] = rsqrtf(var + 1e-5f);
}

// ---------------- normalize + affine + relu ([c][s] layout, native ln params) ------
__global__ __launch_bounds__(256)
void norm_relu_kernel(const float* __restrict__ attn, const float* __restrict__ lnw,
                      const float* __restrict__ lnb, const float* __restrict__ stats,
                      float* __restrict__ out)
{
    size_t i4 = (size_t)blockIdx.x * blockDim.x + threadIdx.x;
    int n  = (int)(i4 >> 16);
    int cs = (int)(i4 & 65535);
    float mu = stats[n * 2 + 0];
    float r  = stats[n * 2 + 1];
    float4 x = ((const float4*)attn)[i4];
    float4 w = ((const float4*)lnw)[cs];
    float4 b = ((const float4*)lnb)[cs];
    float4 y;
    y.x = to_tf32(fmaxf(fmaf((x.x - mu) * r, w.x, b.x), 0.f));
    y.y = to_tf32(fmaxf(fmaf((x.y - mu) * r, w.y, b.y), 0.f));
    y.z = to_tf32(fmaxf(fmaf((x.z - mu) * r, w.z, b.z), 0.f));
    y.w = to_tf32(fmaxf(fmaf((x.w - mu) * r, w.w, b.w), 0.f));
    ((float4*)out)[i4] = y;
}

// ---------------- launch ----------------
extern "C" void kernel_launch(void* const* d_in, const int* in_sizes, int n_in,
                              void* d_out, int out_size)
{
    const float* st    = (const float*)d_in[0];
    const float* lt    = (const float*)d_in[1];
    const float* w_st  = (const float*)d_in[2];
    const float* b_st  = (const float*)d_in[3];
    const float* w_lt  = (const float*)d_in[4];
    const float* b_lt  = (const float*)d_in[5];
    const float* w_g   = (const float*)d_in[6];
    const float* b_g   = (const float*)d_in[7];
    const float* ln_w  = (const float*)d_in[8];
    const float* ln_b  = (const float*)d_in[9];
    const float* w_out = (const float*)d_in[10];
    const float* b_out = (const float*)d_in[11];
    float* out = (float*)d_out;

    float *thetaOS, *pg, *sc, *attn, *nrm, *stats;
    float *wstR, *wLG, *bLG, *woutR;
    float2 *part;
    cudaGetSymbolAddress((void**)&thetaOS, g_thetaOS);
    cudaGetSymbolAddress((void**)&pg,      g_pg);
    cudaGetSymbolAddress((void**)&sc,      g_sc);
    cudaGetSymbolAddress((void**)&attn,    g_attn);
    cudaGetSymbolAddress((void**)&nrm,     g_nrm);
    cudaGetSymbolAddress((void**)&part,    g_part);
    cudaGetSymbolAddress((void**)&stats,   g_stats);
    cudaGetSymbolAddress((void**)&wstR,    g_wstR);
    cudaGetSymbolAddress((void**)&wLG,     g_wLG);
    cudaGetSymbolAddress((void**)&bLG,     g_bLG);
    cudaGetSymbolAddress((void**)&woutR,   g_woutR);

    cudaFuncSetAttribute(gemm_mma<0,0,0,0>, cudaFuncAttributeMaxDynamicSharedMemorySize, GEMM_SMEM);
    cudaFuncSetAttribute(gemm_big<0,1>, cudaFuncAttributeMaxDynamicSharedMemorySize, GEMM_BIG_SMEM);
    cudaFuncSetAttribute(gemm_big<1,0>, cudaFuncAttributeMaxDynamicSharedMemorySize, GEMM_BIG_SMEM);
    cudaFuncSetAttribute(gemm_big<0,0>, cudaFuncAttributeMaxDynamicSharedMemorySize, GEMM_BIG_SMEM);

    const float inv_sqrt_lat = 0.044194173824159216f;   // 1/sqrt(512)

    // prepass: weight rounding + bias stacking (2 launches; LN transposes eliminated)
    round_copy4_kernel<<<4096, 256>>>(w_st, w_lt, w_g, w_out,
                                      wstR, wLG, wLG + (size_t)512 * C_LT_, woutR);
    stack_bias_kernel<<<4, 256>>>(b_lt, b_g, bLG);

    // 1) theta[o][s] = sum_c w_st[o][c] * st[c][s] + b_st[o]   (big-tile, cvt B, rounded)
    gemm_big<0,1><<<dim3(S_ / 256, LAT_ / 128, NBATCH), 256, GEMM_BIG_SMEM>>>(
        wstR, st, thetaOS, b_st, C_ST_, C_ST_, S_, S_,
        0, (size_t)C_ST_ * S_, (size_t)LAT_ * S_, 1.f, 1);

    // 2) merged phi+g: pg[o2][l] = sum_c wLG[o2][c] * lt[c][l] + bLG[o2]
    gemm_big<0,1><<<dim3(L_ / 256, 1024 / 128, NBATCH), 256, GEMM_BIG_SMEM>>>(
        wLG, lt, pg, bLG, C_LT_, C_LT_, L_, L_,
        0, (size_t)C_LT_ * L_, (size_t)1024 * L_, 1.f, 1);

    // 3) scores[s][l] = (1/sqrt(LAT)) * sum_o theta[o][s] * phi[o][l]  (big-tile, A transposed)
    gemm_big<1,0><<<dim3(L_ / 256, S_ / 128, NBATCH), 256, GEMM_BIG_SMEM>>>(
        thetaOS, pg, sc, nullptr, LAT_, S_, L_, L_,
        (size_t)LAT_ * S_, (size_t)1024 * L_, (size_t)S_ * L_, inv_sqrt_lat, 0);

    // 4) softmax over L (in place, rounded output)
    softmax_kernel<<<NBATCH * S_, 256>>>(sc);

    // 5) attn[c][s] = sum_l g[c][l] * p[s][l]    (NT, m=c n=s)
    gemm_mma<0,0,0,0><<<dim3(S_ / 128, LAT_ / 128, NBATCH), 256, GEMM_SMEM>>>(
        pg + (size_t)512 * L_, sc, attn, nullptr, L_, L_, L_, S_,
        (size_t)1024 * L_, (size_t)S_ * L_, (size_t)LAT_ * S_, 1.f, 0, 0);

    // 6) layernorm stats (two-phase) + normalize + relu (native ln params, rounded)
    ln_part_kernel<<<dim3(16, NBATCH), 256>>>(attn, part);
    ln_final_kernel<<<1, 32>>>(part, stats);
    norm_relu_kernel<<<(NBATCH * LAT_ * S_ / 4) / 256, 256>>>(attn, ln_w, ln_b, stats, nrm);

    // 7) out[o][s] = sum_c w_out[o][c] * nrm[c][s] + b_out[o]  (big-tile, no cvt)
    gemm_big<0,0><<<dim3(S_ / 256, C_ST_ / 128, NBATCH), 256, GEMM_BIG_SMEM>>>(
        woutR, nrm, out, b_out, LAT_, LAT_, S_, S_,
        0, (size_t)LAT_ * S_, (size_t)C_ST_ * S_, 1.f, 0);
}